// round 15
// baseline (speedup 1.0000x reference)
#include <cuda_runtime.h>
#include <cuda_fp16.h>
#include <stdint.h>
#include <math.h>

#define BB 4
#define TT 2048
#define DD 128
#define HH 8
#define DK 16
#define KW 12          // smem K row stride (u32): 8 used + 4 pad
#define VW 68          // smem V^T d-row stride (u32): 64 used + 4 pad

__device__ float    g_Q[BB*TT*DD];
__device__ uint32_t g_Kw[BB*HH*TT*8];      // [bh][row][8]: f16 pairs (cols 2w,2w+1)
__device__ uint32_t g_Vt[BB*HH*DK*(TT/2)]; // [bh][d][p]: f16 pack(V[2p][d],V[2p+1][d])
__device__ float    g_ctx[BB*TT*DD];

__device__ __forceinline__ void mma_f16(float c[4], const uint32_t a[4],
                                        uint32_t b0, uint32_t b1) {
    asm volatile(
        "mma.sync.aligned.m16n8k16.row.col.f32.f16.f16.f32 "
        "{%0,%1,%2,%3}, {%4,%5,%6,%7}, {%8,%9}, {%0,%1,%2,%3};"
        : "+f"(c[0]), "+f"(c[1]), "+f"(c[2]), "+f"(c[3])
        : "r"(a[0]), "r"(a[1]), "r"(a[2]), "r"(a[3]), "r"(b0), "r"(b1));
}
__device__ __forceinline__ uint32_t pack_h2(float lo, float hi) {
    __half2 v = __floats2half2_rn(lo, hi);     // .x = lo half
    return *reinterpret_cast<uint32_t*>(&v);
}
__device__ __forceinline__ float ex2(float x) {
    float y; asm("ex2.approx.f32 %0, %1;" : "=f"(y) : "f"(x)); return y;
}
__device__ __forceinline__ void cpa16(uint32_t dst, const void* src) {
    asm volatile("cp.async.ca.shared.global [%0], [%1], 16;" :: "r"(dst), "l"(src));
}
__device__ __forceinline__ void cpa_wait() {
    asm volatile("cp.async.commit_group;\ncp.async.wait_group 0;" ::: "memory");
}
__device__ __forceinline__ void load_qfrag_f16(const float* Qb, uint32_t a[4], int t) {
    const float sc = 0.360673760f;     // 0.25 * log2(e)
    float2 x0 = *(const float2*)(Qb + 2 * t);
    float2 x1 = *(const float2*)(Qb + 8 * DD + 2 * t);
    float2 x2 = *(const float2*)(Qb + 2 * t + 8);
    float2 x3 = *(const float2*)(Qb + 8 * DD + 2 * t + 8);
    a[0] = pack_h2(sc * x0.x, sc * x0.y);
    a[1] = pack_h2(sc * x1.x, sc * x1.y);
    a[2] = pack_h2(sc * x2.x, sc * x2.y);
    a[3] = pack_h2(sc * x3.x, sc * x3.y);
}

// ---------------------------------------------------------------------------
// Attention: grid (TT/128, BB*HH), 128 threads. Each CTA owns two 64-row
// q-tiles (A, B); tile-B's rowsum pass (MMA+MUFU) is fused into tile-A's
// DRAM-store-bound output pass to fill the idle store slack.
// ---------------------------------------------------------------------------
__global__ void __launch_bounds__(128, 8)
attn_mma_kernel(const float* __restrict__ Qg,
                const uint32_t* __restrict__ Kw,
                const uint32_t* __restrict__ Vt,
                float* __restrict__ attn,
                float* __restrict__ ctx)
{
    __shared__ __align__(16) uint32_t sK[128 * KW];
    __shared__ __align__(16) uint32_t sV[DK * VW];

    const int tid  = threadIdx.x;
    const int lane = tid & 31;
    const int wq   = tid >> 5;
    const int g    = lane >> 2;
    const int t    = lane & 3;

    const int q0 = blockIdx.x * 128;
    const int bh = blockIdx.y;
    const int bb = bh >> 3;
    const int h  = bh & 7;
    const int r0A = q0 + wq * 16 + g;
    const int r0B = r0A + 64;

    const uint32_t sKa = (uint32_t)__cvta_generic_to_shared(sK);
    const uint32_t sVa = (uint32_t)__cvta_generic_to_shared(sV);
    const uint32_t* gkb = Kw + ((size_t)bh * TT + tid) * 8;

    uint32_t aA[4], aB[4];
    load_qfrag_f16(Qg + ((size_t)bb * TT + r0A) * DD + h * DK, aA, t);
    load_qfrag_f16(Qg + ((size_t)bb * TT + r0B) * DD + h * DK, aB, t);

    // ---------------- phase 1: rowsums of tile A (K-only fills) ----------------
    float psA0 = 0.f, psA1 = 0.f;
    for (int kt = 0; kt < TT / 128; kt++) {
        __syncthreads();
        {
            const uint32_t* gk = gkb + (size_t)kt * 128 * 8;
            const uint32_t dk0 = sKa + tid * (KW * 4);
            cpa16(dk0,      gk);
            cpa16(dk0 + 16, gk + 4);
        }
        cpa_wait();
        __syncthreads();
        #pragma unroll 4
        for (int ns = 0; ns < 16; ns++) {
            const int base = (ns * 8 + g) * KW + t;
            float C[4] = {0.f, 0.f, 0.f, 0.f};
            mma_f16(C, aA, sK[base], sK[base + 4]);
            psA0 += ex2(C[0]) + ex2(C[1]);
            psA1 += ex2(C[2]) + ex2(C[3]);
        }
    }
    psA0 += __shfl_xor_sync(0xffffffffu, psA0, 1);
    psA0 += __shfl_xor_sync(0xffffffffu, psA0, 2);
    psA1 += __shfl_xor_sync(0xffffffffu, psA1, 1);
    psA1 += __shfl_xor_sync(0xffffffffu, psA1, 2);
    const float lriA0 = -__log2f(psA0);
    const float lriA1 = -__log2f(psA1);

    // ---------------- phase 2: sweep2(A) fused with sweep1(B) ----------------
    float cc[2][4] = {{0.f,0.f,0.f,0.f},{0.f,0.f,0.f,0.f}};
    float psB0 = 0.f, psB1 = 0.f;
    {
        const size_t arow0 = ((size_t)bh * TT + r0A) * TT;
        const size_t arow1 = arow0 + (size_t)8 * TT;
        for (int kt = 0; kt < TT / 128; kt++) {
            __syncthreads();
            {
                const uint32_t* gk = gkb + (size_t)kt * 128 * 8;
                const uint32_t dk0 = sKa + tid * (KW * 4);
                cpa16(dk0,      gk);
                cpa16(dk0 + 16, gk + 4);
                #pragma unroll
                for (int c2 = 0; c2 < 2; c2++) {
                    const int chunk = tid * 2 + c2;
                    const int d  = chunk >> 4;
                    const int cw = chunk & 15;
                    cpa16(sVa + (d * VW + cw * 4) * 4,
                          Vt + ((size_t)bh * DK + d) * (TT / 2) + kt * 64 + cw * 4);
                }
            }
            cpa_wait();
            __syncthreads();

            #pragma unroll 2
            for (int j = 0; j < 8; j++) {
                uint32_t apk[4];
                #pragma unroll
                for (int nsl = 0; nsl < 2; nsl++) {
                    const int base = ((j * 2 + nsl) * 8 + g) * KW + t;
                    // tile A: normalized outputs
                    float C[4] = {lriA0, lriA0, lriA1, lriA1};
                    mma_f16(C, aA, sK[base], sK[base + 4]);
                    const float p0 = ex2(C[0]);
                    const float p1 = ex2(C[1]);
                    const float p2 = ex2(C[2]);
                    const float p3 = ex2(C[3]);
                    const int col = kt * 128 + j * 16 + nsl * 8 + 2 * t;
                    *(float2*)(attn + arow0 + col) = make_float2(p0, p1);
                    *(float2*)(attn + arow1 + col) = make_float2(p2, p3);
                    apk[nsl ? 2 : 0] = pack_h2(p0, p1);
                    apk[nsl ? 3 : 1] = pack_h2(p2, p3);
                    // tile B: rowsums (rides under A's stores)
                    float D[4] = {0.f, 0.f, 0.f, 0.f};
                    mma_f16(D, aB, sK[base], sK[base + 4]);
                    psB0 += ex2(D[0]) + ex2(D[1]);
                    psB1 += ex2(D[2]) + ex2(D[3]);
                }
                #pragma unroll
                for (int n2 = 0; n2 < 2; n2++) {
                    const int vi = (n2 * 8 + g) * VW + 8 * j + t;
                    mma_f16(cc[n2], apk, sV[vi], sV[vi + 4]);
                }
            }
        }
        #pragma unroll
        for (int n2 = 0; n2 < 2; n2++) {
            float* cp = ctx + ((size_t)bb * TT + r0A) * DD + h * DK + n2 * 8 + 2 * t;
            *(float2*)cp            = make_float2(cc[n2][0], cc[n2][1]);
            *(float2*)(cp + 8 * DD) = make_float2(cc[n2][2], cc[n2][3]);
        }
    }
    psB0 += __shfl_xor_sync(0xffffffffu, psB0, 1);
    psB0 += __shfl_xor_sync(0xffffffffu, psB0, 2);
    psB1 += __shfl_xor_sync(0xffffffffu, psB1, 1);
    psB1 += __shfl_xor_sync(0xffffffffu, psB1, 2);
    const float lriB0 = -__log2f(psB0);
    const float lriB1 = -__log2f(psB1);

    // ---------------- phase 3: sweep2(B) ----------------
    {
        #pragma unroll
        for (int n2 = 0; n2 < 2; n2++)
            #pragma unroll
            for (int i = 0; i < 4; i++) cc[n2][i] = 0.f;
        const size_t arow0 = ((size_t)bh * TT + r0B) * TT;
        const size_t arow1 = arow0 + (size_t)8 * TT;
        for (int kt = 0; kt < TT / 128; kt++) {
            __syncthreads();
            {
                const uint32_t* gk = gkb + (size_t)kt * 128 * 8;
                const uint32_t dk0 = sKa + tid * (KW * 4);
                cpa16(dk0,      gk);
                cpa16(dk0 + 16, gk + 4);
                #pragma unroll
                for (int c2 = 0; c2 < 2; c2++) {
                    const int chunk = tid * 2 + c2;
                    const int d  = chunk >> 4;
                    const int cw = chunk & 15;
                    cpa16(sVa + (d * VW + cw * 4) * 4,
                          Vt + ((size_t)bh * DK + d) * (TT / 2) + kt * 64 + cw * 4);
                }
            }
            cpa_wait();
            __syncthreads();

            #pragma unroll 2
            for (int j = 0; j < 8; j++) {
                uint32_t apk[4];
                #pragma unroll
                for (int nsl = 0; nsl < 2; nsl++) {
                    const int base = ((j * 2 + nsl) * 8 + g) * KW + t;
                    float C[4] = {lriB0, lriB0, lriB1, lriB1};
                    mma_f16(C, aB, sK[base], sK[base + 4]);
                    const float p0 = ex2(C[0]);
                    const float p1 = ex2(C[1]);
                    const float p2 = ex2(C[2]);
                    const float p3 = ex2(C[3]);
                    const int col = kt * 128 + j * 16 + nsl * 8 + 2 * t;
                    *(float2*)(attn + arow0 + col) = make_float2(p0, p1);
                    *(float2*)(attn + arow1 + col) = make_float2(p2, p3);
                    apk[nsl ? 2 : 0] = pack_h2(p0, p1);
                    apk[nsl ? 3 : 1] = pack_h2(p2, p3);
                }
                #pragma unroll
                for (int n2 = 0; n2 < 2; n2++) {
                    const int vi = (n2 * 8 + g) * VW + 8 * j + t;
                    mma_f16(cc[n2], apk, sV[vi], sV[vi + 4]);
                }
            }
        }
        #pragma unroll
        for (int n2 = 0; n2 < 2; n2++) {
            float* cp = ctx + ((size_t)bb * TT + r0B) * DD + h * DK + n2 * 8 + 2 * t;
            *(float2*)cp            = make_float2(cc[n2][0], cc[n2][1]);
            *(float2*)(cp + 8 * DD) = make_float2(cc[n2][2], cc[n2][3]);
        }
    }
}

// ---------------------------------------------------------------------------
// Merged QKV projection: grid (rows/32, 3), 128 threads, 32 rows per block.
// y==0 -> Q fp32; y==1 -> K f16 pairs; y==2 -> V^T f16 pairs
// ---------------------------------------------------------------------------
__global__ void __launch_bounds__(128, 4)
proj3_kernel(const float* __restrict__ q,
             const float* __restrict__ k,
             const float* __restrict__ v,
             const float* __restrict__ Wq, const float* __restrict__ bq,
             const float* __restrict__ Wk, const float* __restrict__ bk,
             const float* __restrict__ Wv, const float* __restrict__ bv,
             float* __restrict__ Qd,
             uint32_t* __restrict__ Kw,
             uint32_t* __restrict__ Vt)
{
    const float* X; const float* W; const float* bias;
    if (blockIdx.y == 0)      { X = q; W = Wq; bias = bq; }
    else if (blockIdx.y == 1) { X = k; W = Wk; bias = bk; }
    else                      { X = v; W = Wv; bias = bv; }

    __shared__ float xs[32][132];
    const int tid  = threadIdx.x;
    const int row0 = blockIdx.x * 32;

    #pragma unroll
    for (int r = 0; r < 32; r++)
        xs[r][tid] = X[(size_t)(row0 + r) * DD + tid];
    __syncthreads();

    float acc[32];
    const float bvv = bias[tid];
    #pragma unroll
    for (int r = 0; r < 32; r++) acc[r] = bvv;

    #pragma unroll 2
    for (int kk = 0; kk < DD; kk += 4) {
        const float w0 = W[(kk + 0) * DD + tid];
        const float w1 = W[(kk + 1) * DD + tid];
        const float w2 = W[(kk + 2) * DD + tid];
        const float w3 = W[(kk + 3) * DD + tid];
        #pragma unroll
        for (int r = 0; r < 32; r++) {
            const float4 xv = *(const float4*)&xs[r][kk];
            acc[r] = fmaf(xv.x, w0, fmaf(xv.y, w1, fmaf(xv.z, w2, fmaf(xv.w, w3, acc[r]))));
        }
    }

    if (blockIdx.y == 0) {
        #pragma unroll
        for (int r = 0; r < 32; r++)
            Qd[(size_t)(row0 + r) * DD + tid] = acc[r];
        return;
    }

    __syncthreads();
    #pragma unroll
    for (int r = 0; r < 32; r++) xs[r][tid] = acc[r];
    __syncthreads();

    const int bbat = row0 >> 11;
    const int trow = row0 & 2047;

    if (blockIdx.y == 1) {
        // K: 32 rows x 8 heads x 8 f16-pair words = 2048 words
        #pragma unroll
        for (int i = 0; i < 16; i++) {
            const int widx = i * 128 + tid;      // 0..2047
            const int r    = widx >> 6;          // 0..31
            const int rem  = widx & 63;
            const int hh2  = rem >> 3;           // head
            const int w    = rem & 7;
            const int c    = hh2 * DK + w * 2;
            const uint32_t word = pack_h2(xs[r][c], xs[r][c + 1]);
            Kw[((size_t)(bbat * HH + hh2) * TT + trow + r) * 8 + w] = word;
        }
    } else {
        // V^T: word = pack(V[2p][d], V[2p+1][d]); 32 rows = 16 pairs x 128 hd
        const int p0 = trow >> 1;
        #pragma unroll
        for (int i = 0; i < 16; i++) {
            const int widx = i * 128 + tid;      // 0..2047
            const int hd  = widx >> 4;           // 0..127
            const int pl  = widx & 15;           // 0..15
            const int hh2 = hd >> 4, d = hd & 15;
            const int c   = hh2 * DK + d;
            const uint32_t word = pack_h2(xs[2 * pl][c], xs[2 * pl + 1][c]);
            Vt[((size_t)(bbat * HH + hh2) * DK + d) * (TT / 2) + p0 + pl] = word;
        }
    }
}

// ---------------------------------------------------------------------------
// Output projection + residual + LayerNorm
// ---------------------------------------------------------------------------
__global__ void out_kernel(const float* __restrict__ ctxg,
                           const float* __restrict__ Wo,
                           const float* __restrict__ bo,
                           const float* __restrict__ resid,
                           const float* __restrict__ gamma,
                           const float* __restrict__ beta,
                           float* __restrict__ out)
{
    __shared__ float xs[16][132];
    __shared__ float mrow[16], rrow[16];
    const int tid  = threadIdx.x;
    const int row0 = blockIdx.x * 16;

    #pragma unroll
    for (int r = 0; r < 16; r++)
        xs[r][tid] = ctxg[(size_t)(row0 + r) * DD + tid];
    __syncthreads();

    float acc[16];
    const float bv = bo[tid];
    #pragma unroll
    for (int r = 0; r < 16; r++) acc[r] = bv;

    #pragma unroll 4
    for (int kk = 0; kk < DD; kk += 4) {
        const float w0 = Wo[(kk + 0) * DD + tid];
        const float w1 = Wo[(kk + 1) * DD + tid];
        const float w2 = Wo[(kk + 2) * DD + tid];
        const float w3 = Wo[(kk + 3) * DD + tid];
        #pragma unroll
        for (int r = 0; r < 16; r++) {
            const float4 xv = *(const float4*)&xs[r][kk];
            acc[r] = fmaf(xv.x, w0, fmaf(xv.y, w1, fmaf(xv.z, w2, fmaf(xv.w, w3, acc[r]))));
        }
    }
    __syncthreads();

    #pragma unroll
    for (int r = 0; r < 16; r++) {
        acc[r] += resid[(size_t)(row0 + r) * DD + tid];
        xs[r][tid] = acc[r];
    }
    __syncthreads();

    {
        const int r = tid >> 3, l8 = tid & 7;
        float s = 0.f, s2 = 0.f;
        for (int c = l8; c < 128; c += 8) {
            const float v = xs[r][c];
            s += v; s2 = fmaf(v, v, s2);
        }
        #pragma unroll
        for (int off = 4; off > 0; off >>= 1) {
            s  += __shfl_down_sync(0xffffffffu, s,  off, 8);
            s2 += __shfl_down_sync(0xffffffffu, s2, off, 8);
        }
        if (l8 == 0) {
            const float m   = s * (1.f / 128.f);
            const float var = s2 * (1.f / 128.f) - m * m;
            mrow[r] = m;
            rrow[r] = rsqrtf(var + 1e-5f);
        }
    }
    __syncthreads();

    const float gm = gamma[tid], bt = beta[tid];
    #pragma unroll
    for (int r = 0; r < 16; r++)
        out[(size_t)(row0 + r) * DD + tid] = (acc[r] - mrow[r]) * rrow[r] * gm + bt;
}

// ---------------------------------------------------------------------------
extern "C" void kernel_launch(void* const* d_in, const int* in_sizes, int n_in,
                              void* d_out, int out_size)
{
    const float* queries = (const float*)d_in[0];
    const float* keys    = (const float*)d_in[1];
    const float* values  = (const float*)d_in[2];
    const float* Wq      = (const float*)d_in[3];
    const float* bq      = (const float*)d_in[4];
    const float* Wk      = (const float*)d_in[5];
    const float* bk      = (const float*)d_in[6];
    const float* Wv      = (const float*)d_in[7];
    const float* bv      = (const float*)d_in[8];
    const float* Wo      = (const float*)d_in[9];
    const float* bo      = (const float*)d_in[10];
    const float* gamma   = (const float*)d_in[11];
    const float* beta    = (const float*)d_in[12];

    float* out  = (float*)d_out;
    float* attn = out + (size_t)BB * TT * DD;

    float *Qd, *Cd; uint32_t *Kwp, *Vtp;
    cudaGetSymbolAddress((void**)&Qd,  g_Q);
    cudaGetSymbolAddress((void**)&Kwp, g_Kw);
    cudaGetSymbolAddress((void**)&Vtp, g_Vt);
    cudaGetSymbolAddress((void**)&Cd,  g_ctx);

    const int rows = BB * TT;
    proj3_kernel<<<dim3(rows / 32, 3), 128>>>(queries, keys, values,
                                              Wq, bq, Wk, bk, Wv, bv,
                                              Qd, Kwp, Vtp);

    attn_mma_kernel<<<dim3(TT / 128, BB * HH), 128>>>(Qd, Kwp, Vtp, attn, Cd);

    out_kernel<<<rows / 16, 128>>>(Cd, Wo, bo, queries, gamma, beta, out);
}

// round 16
// speedup vs baseline: 1.1483x; 1.1483x over previous
#include <cuda_runtime.h>
#include <cuda_fp16.h>
#include <stdint.h>
#include <math.h>

#define BB 4
#define TT 2048
#define DD 128
#define HH 8
#define DK 16
#define KW 12          // smem K row stride (u32): 8 used + 4 pad
#define VW 68          // smem V^T d-row stride (u32): 64 used + 4 pad

__device__ float    g_Q[BB*TT*DD];
__device__ uint32_t g_Kw[BB*HH*TT*8];      // [bh][row][8]: f16 pairs (cols 2w,2w+1)
__device__ uint32_t g_Vt[BB*HH*DK*(TT/2)]; // [bh][d][p]: f16 pack(V[2p][d],V[2p+1][d])
__device__ float    g_ctx[BB*TT*DD];

__device__ __forceinline__ void mma_f16(float c[4], const uint32_t a[4],
                                        uint32_t b0, uint32_t b1) {
    asm volatile(
        "mma.sync.aligned.m16n8k16.row.col.f32.f16.f16.f32 "
        "{%0,%1,%2,%3}, {%4,%5,%6,%7}, {%8,%9}, {%0,%1,%2,%3};"
        : "+f"(c[0]), "+f"(c[1]), "+f"(c[2]), "+f"(c[3])
        : "r"(a[0]), "r"(a[1]), "r"(a[2]), "r"(a[3]), "r"(b0), "r"(b1));
}
__device__ __forceinline__ uint32_t pack_h2(float lo, float hi) {
    __half2 v = __floats2half2_rn(lo, hi);     // .x = lo half
    return *reinterpret_cast<uint32_t*>(&v);
}
__device__ __forceinline__ float ex2(float x) {
    float y; asm("ex2.approx.f32 %0, %1;" : "=f"(y) : "f"(x)); return y;
}
__device__ __forceinline__ void cpa16(uint32_t dst, const void* src) {
    asm volatile("cp.async.ca.shared.global [%0], [%1], 16;" :: "r"(dst), "l"(src));
}
__device__ __forceinline__ void cpa_wait() {
    asm volatile("cp.async.commit_group;\ncp.async.wait_group 0;" ::: "memory");
}
__device__ __forceinline__ void st_cs64(float* p, float a, float b) {
    asm volatile("st.global.cs.v2.f32 [%0], {%1, %2};" :: "l"(p), "f"(a), "f"(b) : "memory");
}

// ---------------------------------------------------------------------------
// Attention: grid (TT/64, BB*HH), 128 threads = 4 warps x one m16 fragment.
// Scores: single f16 MMA, identical in both sweeps (rows sum exactly to 1).
// ---------------------------------------------------------------------------
__global__ void __launch_bounds__(128, 8)
attn_mma_kernel(const float* __restrict__ Qg,
                const uint32_t* __restrict__ Kw,
                const uint32_t* __restrict__ Vt,
                float* __restrict__ attn,
                float* __restrict__ ctx)
{
    __shared__ __align__(16) uint32_t sK[128 * KW];
    __shared__ __align__(16) uint32_t sV[DK * VW];

    const int tid  = threadIdx.x;
    const int lane = tid & 31;
    const int wq   = tid >> 5;
    const int g    = lane >> 2;
    const int t    = lane & 3;

    const int q0 = blockIdx.x * 64;
    const int bh = blockIdx.y;
    const int bb = bh >> 3;
    const int h  = bh & 7;
    const int r0 = q0 + wq * 16 + g;

    const uint32_t sKa = (uint32_t)__cvta_generic_to_shared(sK);
    const uint32_t sVa = (uint32_t)__cvta_generic_to_shared(sV);
    const uint32_t* gkb = Kw + ((size_t)bh * TT + tid) * 8;

    // Q fragment: f16, prescaled by 0.25*log2(e)
    uint32_t ahi[4];
    {
        const float sc = 0.360673760f;     // 0.25 * log2(e)
        const float* Qb = Qg + ((size_t)bb * TT + r0) * DD + h * DK;
        float2 x0 = *(const float2*)(Qb + 2 * t);
        float2 x1 = *(const float2*)(Qb + 8 * DD + 2 * t);
        float2 x2 = *(const float2*)(Qb + 2 * t + 8);
        float2 x3 = *(const float2*)(Qb + 8 * DD + 2 * t + 8);
        ahi[0] = pack_h2(sc * x0.x, sc * x0.y);
        ahi[1] = pack_h2(sc * x1.x, sc * x1.y);
        ahi[2] = pack_h2(sc * x2.x, sc * x2.y);
        ahi[3] = pack_h2(sc * x3.x, sc * x3.y);
    }

    // ---------------- sweep 1: rowsums ----------------
    float ps0 = 0.f, ps1 = 0.f;
    for (int kt = 0; kt < TT / 128; kt++) {
        __syncthreads();
        {
            const uint32_t* gk = gkb + (size_t)kt * 128 * 8;
            const uint32_t dk0 = sKa + tid * (KW * 4);
            cpa16(dk0,      gk);
            cpa16(dk0 + 16, gk + 4);
        }
        cpa_wait();
        __syncthreads();
        #pragma unroll 8
        for (int ns = 0; ns < 16; ns++) {
            const int base = (ns * 8 + g) * KW + t;
            float C[4] = {0.f, 0.f, 0.f, 0.f};
            mma_f16(C, ahi, sK[base], sK[base + 4]);
            ps0 += ex2(C[0]) + ex2(C[1]);
            ps1 += ex2(C[2]) + ex2(C[3]);
        }
    }
    ps0 += __shfl_xor_sync(0xffffffffu, ps0, 1);
    ps0 += __shfl_xor_sync(0xffffffffu, ps0, 2);
    ps1 += __shfl_xor_sync(0xffffffffu, ps1, 1);
    ps1 += __shfl_xor_sync(0xffffffffu, ps1, 2);
    const float lri0 = -__log2f(ps0);
    const float lri1 = -__log2f(ps1);

    // ---------------- sweep 2: scores, attn stores, PV ----------------
    float cc[2][4] = {{0.f,0.f,0.f,0.f},{0.f,0.f,0.f,0.f}};
    const size_t arow0 = ((size_t)bh * TT + r0) * TT;
    const size_t arow1 = arow0 + (size_t)8 * TT;

    for (int kt = 0; kt < TT / 128; kt++) {
        __syncthreads();
        {
            const uint32_t* gk = gkb + (size_t)kt * 128 * 8;
            const uint32_t dk0 = sKa + tid * (KW * 4);
            cpa16(dk0,      gk);
            cpa16(dk0 + 16, gk + 4);
            #pragma unroll
            for (int c2 = 0; c2 < 2; c2++) {
                const int chunk = tid * 2 + c2;       // 0..255
                const int d  = chunk >> 4;
                const int cw = chunk & 15;
                cpa16(sVa + (d * VW + cw * 4) * 4,
                      Vt + ((size_t)bh * DK + d) * (TT / 2) + kt * 64 + cw * 4);
            }
        }
        cpa_wait();
        __syncthreads();

        #pragma unroll 4
        for (int j = 0; j < 8; j++) {
            uint32_t apk[4];
            #pragma unroll
            for (int nsl = 0; nsl < 2; nsl++) {
                const int base = ((j * 2 + nsl) * 8 + g) * KW + t;
                float C[4] = {lri0, lri0, lri1, lri1};
                mma_f16(C, ahi, sK[base], sK[base + 4]);
                const float p0 = ex2(C[0]);
                const float p1 = ex2(C[1]);
                const float p2 = ex2(C[2]);
                const float p3 = ex2(C[3]);
                const int col = kt * 128 + j * 16 + nsl * 8 + 2 * t;
                st_cs64(attn + arow0 + col, p0, p1);
                st_cs64(attn + arow1 + col, p2, p3);
                apk[nsl ? 2 : 0] = pack_h2(p0, p1);
                apk[nsl ? 3 : 1] = pack_h2(p2, p3);
            }
            #pragma unroll
            for (int n2 = 0; n2 < 2; n2++) {
                const int vi = (n2 * 8 + g) * VW + 8 * j + t;
                mma_f16(cc[n2], apk, sV[vi], sV[vi + 4]);
            }
        }
    }

    #pragma unroll
    for (int n2 = 0; n2 < 2; n2++) {
        float* cp = ctx + ((size_t)bb * TT + r0) * DD + h * DK + n2 * 8 + 2 * t;
        *(float2*)cp            = make_float2(cc[n2][0], cc[n2][1]);
        *(float2*)(cp + 8 * DD) = make_float2(cc[n2][2], cc[n2][3]);
    }
}

// ---------------------------------------------------------------------------
// Merged QKV projection: grid (rows/32, 3), 128 threads, 32 rows per block.
// y==0 -> Q fp32; y==1 -> K f16 pairs; y==2 -> V^T f16 pairs
// ---------------------------------------------------------------------------
__global__ void __launch_bounds__(128, 4)
proj3_kernel(const float* __restrict__ q,
             const float* __restrict__ k,
             const float* __restrict__ v,
             const float* __restrict__ Wq, const float* __restrict__ bq,
             const float* __restrict__ Wk, const float* __restrict__ bk,
             const float* __restrict__ Wv, const float* __restrict__ bv,
             float* __restrict__ Qd,
             uint32_t* __restrict__ Kw,
             uint32_t* __restrict__ Vt)
{
    const float* X; const float* W; const float* bias;
    if (blockIdx.y == 0)      { X = q; W = Wq; bias = bq; }
    else if (blockIdx.y == 1) { X = k; W = Wk; bias = bk; }
    else                      { X = v; W = Wv; bias = bv; }

    __shared__ float xs[32][132];
    const int tid  = threadIdx.x;
    const int row0 = blockIdx.x * 32;

    #pragma unroll
    for (int r = 0; r < 32; r++)
        xs[r][tid] = X[(size_t)(row0 + r) * DD + tid];
    __syncthreads();

    float acc[32];
    const float bvv = bias[tid];
    #pragma unroll
    for (int r = 0; r < 32; r++) acc[r] = bvv;

    #pragma unroll 2
    for (int kk = 0; kk < DD; kk += 4) {
        const float w0 = W[(kk + 0) * DD + tid];
        const float w1 = W[(kk + 1) * DD + tid];
        const float w2 = W[(kk + 2) * DD + tid];
        const float w3 = W[(kk + 3) * DD + tid];
        #pragma unroll
        for (int r = 0; r < 32; r++) {
            const float4 xv = *(const float4*)&xs[r][kk];
            acc[r] = fmaf(xv.x, w0, fmaf(xv.y, w1, fmaf(xv.z, w2, fmaf(xv.w, w3, acc[r]))));
        }
    }

    if (blockIdx.y == 0) {
        #pragma unroll
        for (int r = 0; r < 32; r++)
            Qd[(size_t)(row0 + r) * DD + tid] = acc[r];
        return;
    }

    __syncthreads();
    #pragma unroll
    for (int r = 0; r < 32; r++) xs[r][tid] = acc[r];
    __syncthreads();

    const int bbat = row0 >> 11;
    const int trow = row0 & 2047;

    if (blockIdx.y == 1) {
        // K: 32 rows x 8 heads x 8 f16-pair words = 2048 words
        #pragma unroll
        for (int i = 0; i < 16; i++) {
            const int widx = i * 128 + tid;      // 0..2047
            const int r    = widx >> 6;          // 0..31
            const int rem  = widx & 63;
            const int hh2  = rem >> 3;           // head
            const int w    = rem & 7;
            const int c    = hh2 * DK + w * 2;
            const uint32_t word = pack_h2(xs[r][c], xs[r][c + 1]);
            Kw[((size_t)(bbat * HH + hh2) * TT + trow + r) * 8 + w] = word;
        }
    } else {
        // V^T: word = pack(V[2p][d], V[2p+1][d]); 32 rows = 16 pairs x 128 hd
        const int p0 = trow >> 1;
        #pragma unroll
        for (int i = 0; i < 16; i++) {
            const int widx = i * 128 + tid;      // 0..2047
            const int hd  = widx >> 4;           // 0..127
            const int pl  = widx & 15;           // 0..15
            const int hh2 = hd >> 4, d = hd & 15;
            const int c   = hh2 * DK + d;
            const uint32_t word = pack_h2(xs[2 * pl][c], xs[2 * pl + 1][c]);
            Vt[((size_t)(bbat * HH + hh2) * DK + d) * (TT / 2) + p0 + pl] = word;
        }
    }
}

// ---------------------------------------------------------------------------
// Output projection + residual + LayerNorm
// ---------------------------------------------------------------------------
__global__ void out_kernel(const float* __restrict__ ctxg,
                           const float* __restrict__ Wo,
                           const float* __restrict__ bo,
                           const float* __restrict__ resid,
                           const float* __restrict__ gamma,
                           const float* __restrict__ beta,
                           float* __restrict__ out)
{
    __shared__ float xs[16][132];
    __shared__ float mrow[16], rrow[16];
    const int tid  = threadIdx.x;
    const int row0 = blockIdx.x * 16;

    #pragma unroll
    for (int r = 0; r < 16; r++)
        xs[r][tid] = ctxg[(size_t)(row0 + r) * DD + tid];
    __syncthreads();

    float acc[16];
    const float bv = bo[tid];
    #pragma unroll
    for (int r = 0; r < 16; r++) acc[r] = bv;

    #pragma unroll 4
    for (int kk = 0; kk < DD; kk += 4) {
        const float w0 = Wo[(kk + 0) * DD + tid];
        const float w1 = Wo[(kk + 1) * DD + tid];
        const float w2 = Wo[(kk + 2) * DD + tid];
        const float w3 = Wo[(kk + 3) * DD + tid];
        #pragma unroll
        for (int r = 0; r < 16; r++) {
            const float4 xv = *(const float4*)&xs[r][kk];
            acc[r] = fmaf(xv.x, w0, fmaf(xv.y, w1, fmaf(xv.z, w2, fmaf(xv.w, w3, acc[r]))));
        }
    }
    __syncthreads();

    #pragma unroll
    for (int r = 0; r < 16; r++) {
        acc[r] += resid[(size_t)(row0 + r) * DD + tid];
        xs[r][tid] = acc[r];
    }
    __syncthreads();

    {
        const int r = tid >> 3, l8 = tid & 7;
        float s = 0.f, s2 = 0.f;
        for (int c = l8; c < 128; c += 8) {
            const float v = xs[r][c];
            s += v; s2 = fmaf(v, v, s2);
        }
        #pragma unroll
        for (int off = 4; off > 0; off >>= 1) {
            s  += __shfl_down_sync(0xffffffffu, s,  off, 8);
            s2 += __shfl_down_sync(0xffffffffu, s2, off, 8);
        }
        if (l8 == 0) {
            const float m   = s * (1.f / 128.f);
            const float var = s2 * (1.f / 128.f) - m * m;
            mrow[r] = m;
            rrow[r] = rsqrtf(var + 1e-5f);
        }
    }
    __syncthreads();

    const float gm = gamma[tid], bt = beta[tid];
    #pragma unroll
    for (int r = 0; r < 16; r++)
        out[(size_t)(row0 + r) * DD + tid] = (acc[r] - mrow[r]) * rrow[r] * gm + bt;
}

// ---------------------------------------------------------------------------
extern "C" void kernel_launch(void* const* d_in, const int* in_sizes, int n_in,
                              void* d_out, int out_size)
{
    const float* queries = (const float*)d_in[0];
    const float* keys    = (const float*)d_in[1];
    const float* values  = (const float*)d_in[2];
    const float* Wq      = (const float*)d_in[3];
    const float* bq      = (const float*)d_in[4];
    const float* Wk      = (const float*)d_in[5];
    const float* bk      = (const float*)d_in[6];
    const float* Wv      = (const float*)d_in[7];
    const float* bv      = (const float*)d_in[8];
    const float* Wo      = (const float*)d_in[9];
    const float* bo      = (const float*)d_in[10];
    const float* gamma   = (const float*)d_in[11];
    const float* beta    = (const float*)d_in[12];

    float* out  = (float*)d_out;
    float* attn = out + (size_t)BB * TT * DD;

    float *Qd, *Cd; uint32_t *Kwp, *Vtp;
    cudaGetSymbolAddress((void**)&Qd,  g_Q);
    cudaGetSymbolAddress((void**)&Kwp, g_Kw);
    cudaGetSymbolAddress((void**)&Vtp, g_Vt);
    cudaGetSymbolAddress((void**)&Cd,  g_ctx);

    const int rows = BB * TT;
    proj3_kernel<<<dim3(rows / 32, 3), 128>>>(queries, keys, values,
                                              Wq, bq, Wk, bk, Wv, bv,
                                              Qd, Kwp, Vtp);

    attn_mma_kernel<<<dim3(TT / 64, BB * HH), 128>>>(Qd, Kwp, Vtp, attn, Cd);

    out_kernel<<<rows / 16, 128>>>(Cd, Wo, bo, queries, gamma, beta, out);
}

// round 17
// speedup vs baseline: 1.2537x; 1.0918x over previous
#include <cuda_runtime.h>
#include <cuda_fp16.h>
#include <stdint.h>
#include <math.h>

#define BB 4
#define TT 2048
#define DD 128
#define HH 8
#define DK 16
#define KW 12          // attn smem K row stride (u32): 8 used + 4 pad
#define VW 68          // attn smem V^T d-row stride (u32): 64 used + 4 pad
#define PW 68          // proj smem row stride (u32 words): 64 used + 4 pad

__device__ float    g_Q[BB*TT*DD];
__device__ uint32_t g_Kw[BB*HH*TT*8];      // [bh][row][8]: f16 pairs (cols 2w,2w+1)
__device__ uint32_t g_Vt[BB*HH*DK*(TT/2)]; // [bh][d][p]: f16 pack(V[2p][d],V[2p+1][d])
__device__ float    g_ctx[BB*TT*DD];
__device__ uint32_t g_Wt[3*DD*64];         // [y][n][kw]: f16 pack(W[2kw][n],W[2kw+1][n])

__device__ __forceinline__ void mma_f16(float c[4], const uint32_t a[4],
                                        uint32_t b0, uint32_t b1) {
    asm volatile(
        "mma.sync.aligned.m16n8k16.row.col.f32.f16.f16.f32 "
        "{%0,%1,%2,%3}, {%4,%5,%6,%7}, {%8,%9}, {%0,%1,%2,%3};"
        : "+f"(c[0]), "+f"(c[1]), "+f"(c[2]), "+f"(c[3])
        : "r"(a[0]), "r"(a[1]), "r"(a[2]), "r"(a[3]), "r"(b0), "r"(b1));
}
__device__ __forceinline__ uint32_t pack_h2(float lo, float hi) {
    __half2 v = __floats2half2_rn(lo, hi);     // .x = lo half
    return *reinterpret_cast<uint32_t*>(&v);
}
__device__ __forceinline__ void split_h2(float a, float b,
                                         uint32_t& hi, uint32_t& lo) {
    __half2 h2 = __floats2half2_rn(a, b);
    __half2 l2 = __floats2half2_rn(a - __half2float(h2.x),
                                   b - __half2float(h2.y));
    hi = *reinterpret_cast<uint32_t*>(&h2);
    lo = *reinterpret_cast<uint32_t*>(&l2);
}
__device__ __forceinline__ float ex2(float x) {
    float y; asm("ex2.approx.f32 %0, %1;" : "=f"(y) : "f"(x)); return y;
}
__device__ __forceinline__ void cpa16(uint32_t dst, const void* src) {
    asm volatile("cp.async.ca.shared.global [%0], [%1], 16;" :: "r"(dst), "l"(src));
}
__device__ __forceinline__ void cpa_wait() {
    asm volatile("cp.async.commit_group;\ncp.async.wait_group 0;" ::: "memory");
}
__device__ __forceinline__ void st_cs64(float* p, float a, float b) {
    asm volatile("st.global.cs.v2.f32 [%0], {%1, %2};" :: "l"(p), "f"(a), "f"(b) : "memory");
}

// ---------------------------------------------------------------------------
// Attention (round-16 best, unchanged): grid (TT/64, BB*HH), 128 threads.
// ---------------------------------------------------------------------------
__global__ void __launch_bounds__(128, 8)
attn_mma_kernel(const float* __restrict__ Qg,
                const uint32_t* __restrict__ Kw,
                const uint32_t* __restrict__ Vt,
                float* __restrict__ attn,
                float* __restrict__ ctx)
{
    __shared__ __align__(16) uint32_t sK[128 * KW];
    __shared__ __align__(16) uint32_t sV[DK * VW];

    const int tid  = threadIdx.x;
    const int lane = tid & 31;
    const int wq   = tid >> 5;
    const int g    = lane >> 2;
    const int t    = lane & 3;

    const int q0 = blockIdx.x * 64;
    const int bh = blockIdx.y;
    const int bb = bh >> 3;
    const int h  = bh & 7;
    const int r0 = q0 + wq * 16 + g;

    const uint32_t sKa = (uint32_t)__cvta_generic_to_shared(sK);
    const uint32_t sVa = (uint32_t)__cvta_generic_to_shared(sV);
    const uint32_t* gkb = Kw + ((size_t)bh * TT + tid) * 8;

    uint32_t ahi[4];
    {
        const float sc = 0.360673760f;     // 0.25 * log2(e)
        const float* Qb = Qg + ((size_t)bb * TT + r0) * DD + h * DK;
        float2 x0 = *(const float2*)(Qb + 2 * t);
        float2 x1 = *(const float2*)(Qb + 8 * DD + 2 * t);
        float2 x2 = *(const float2*)(Qb + 2 * t + 8);
        float2 x3 = *(const float2*)(Qb + 8 * DD + 2 * t + 8);
        ahi[0] = pack_h2(sc * x0.x, sc * x0.y);
        ahi[1] = pack_h2(sc * x1.x, sc * x1.y);
        ahi[2] = pack_h2(sc * x2.x, sc * x2.y);
        ahi[3] = pack_h2(sc * x3.x, sc * x3.y);
    }

    float ps0 = 0.f, ps1 = 0.f;
    for (int kt = 0; kt < TT / 128; kt++) {
        __syncthreads();
        {
            const uint32_t* gk = gkb + (size_t)kt * 128 * 8;
            const uint32_t dk0 = sKa + tid * (KW * 4);
            cpa16(dk0,      gk);
            cpa16(dk0 + 16, gk + 4);
        }
        cpa_wait();
        __syncthreads();
        #pragma unroll 8
        for (int ns = 0; ns < 16; ns++) {
            const int base = (ns * 8 + g) * KW + t;
            float C[4] = {0.f, 0.f, 0.f, 0.f};
            mma_f16(C, ahi, sK[base], sK[base + 4]);
            ps0 += ex2(C[0]) + ex2(C[1]);
            ps1 += ex2(C[2]) + ex2(C[3]);
        }
    }
    ps0 += __shfl_xor_sync(0xffffffffu, ps0, 1);
    ps0 += __shfl_xor_sync(0xffffffffu, ps0, 2);
    ps1 += __shfl_xor_sync(0xffffffffu, ps1, 1);
    ps1 += __shfl_xor_sync(0xffffffffu, ps1, 2);
    const float lri0 = -__log2f(ps0);
    const float lri1 = -__log2f(ps1);

    float cc[2][4] = {{0.f,0.f,0.f,0.f},{0.f,0.f,0.f,0.f}};
    const size_t arow0 = ((size_t)bh * TT + r0) * TT;
    const size_t arow1 = arow0 + (size_t)8 * TT;

    for (int kt = 0; kt < TT / 128; kt++) {
        __syncthreads();
        {
            const uint32_t* gk = gkb + (size_t)kt * 128 * 8;
            const uint32_t dk0 = sKa + tid * (KW * 4);
            cpa16(dk0,      gk);
            cpa16(dk0 + 16, gk + 4);
            #pragma unroll
            for (int c2 = 0; c2 < 2; c2++) {
                const int chunk = tid * 2 + c2;       // 0..255
                const int d  = chunk >> 4;
                const int cw = chunk & 15;
                cpa16(sVa + (d * VW + cw * 4) * 4,
                      Vt + ((size_t)bh * DK + d) * (TT / 2) + kt * 64 + cw * 4);
            }
        }
        cpa_wait();
        __syncthreads();

        #pragma unroll 4
        for (int j = 0; j < 8; j++) {
            uint32_t apk[4];
            #pragma unroll
            for (int nsl = 0; nsl < 2; nsl++) {
                const int base = ((j * 2 + nsl) * 8 + g) * KW + t;
                float C[4] = {lri0, lri0, lri1, lri1};
                mma_f16(C, ahi, sK[base], sK[base + 4]);
                const float p0 = ex2(C[0]);
                const float p1 = ex2(C[1]);
                const float p2 = ex2(C[2]);
                const float p3 = ex2(C[3]);
                const int col = kt * 128 + j * 16 + nsl * 8 + 2 * t;
                st_cs64(attn + arow0 + col, p0, p1);
                st_cs64(attn + arow1 + col, p2, p3);
                apk[nsl ? 2 : 0] = pack_h2(p0, p1);
                apk[nsl ? 3 : 1] = pack_h2(p2, p3);
            }
            #pragma unroll
            for (int n2 = 0; n2 < 2; n2++) {
                const int vi = (n2 * 8 + g) * VW + 8 * j + t;
                mma_f16(cc[n2], apk, sV[vi], sV[vi + 4]);
            }
        }
    }

    #pragma unroll
    for (int n2 = 0; n2 < 2; n2++) {
        float* cp = ctx + ((size_t)bb * TT + r0) * DD + h * DK + n2 * 8 + 2 * t;
        *(float2*)cp            = make_float2(cc[n2][0], cc[n2][1]);
        *(float2*)(cp + 8 * DD) = make_float2(cc[n2][2], cc[n2][3]);
    }
}

// ---------------------------------------------------------------------------
// wt_pack: W[128][128] fp32 -> f16 k-pair words [n][kw]. grid 3, 128 thr.
// ---------------------------------------------------------------------------
__global__ void wt_pack_kernel(const float* __restrict__ Wq,
                               const float* __restrict__ Wk,
                               const float* __restrict__ Wv,
                               uint32_t* __restrict__ Wt)
{
    const float* W = (blockIdx.x == 0) ? Wq : (blockIdx.x == 1) ? Wk : Wv;
    uint32_t* out = Wt + blockIdx.x * DD * 64;
    const int n = threadIdx.x;
    #pragma unroll 4
    for (int kw = 0; kw < 64; kw++) {
        const float a = W[(2 * kw) * DD + n];
        const float b = W[(2 * kw + 1) * DD + n];
        out[n * 64 + kw] = pack_h2(a, b);
    }
}

// ---------------------------------------------------------------------------
// proj3_mma: grid (128, 3), 128 threads, 64 rows per block.
// C = X @ W + b via f16 mma (X split hi/lo, W single f16).
// Epilogue: stage C to smem fp32, then pack per-y output format.
// smem (dynamic): sXh[64*PW] | sXl[64*PW] | sW[128*PW]   (u32 words)
//                 xsF fp32 [64][132] overlays sXh+sXl after mainloop.
// ---------------------------------------------------------------------------
__global__ void __launch_bounds__(128, 3)
proj3_mma_kernel(const float* __restrict__ q,
                 const float* __restrict__ k,
                 const float* __restrict__ v,
                 const uint32_t* __restrict__ Wt,
                 const float* __restrict__ bq,
                 const float* __restrict__ bk,
                 const float* __restrict__ bv,
                 float* __restrict__ Qd,
                 uint32_t* __restrict__ Kw,
                 uint32_t* __restrict__ Vt)
{
    extern __shared__ __align__(16) uint32_t dsm[];
    uint32_t* sXh = dsm;                 // 64*PW
    uint32_t* sXl = dsm + 64 * PW;       // 64*PW
    uint32_t* sW  = dsm + 128 * PW;      // 128*PW
    float*    xsF = (float*)dsm;         // overlay (64*132 floats <= 128*PW words)

    const int tid  = threadIdx.x;
    const int lane = tid & 31;
    const int wq   = tid >> 5;
    const int g    = lane >> 2;
    const int t    = lane & 3;

    const int row0 = blockIdx.x * 64;
    const int y    = blockIdx.y;
    const float* X    = (y == 0) ? q  : (y == 1) ? k  : v;
    const float* bias = (y == 0) ? bq : (y == 1) ? bk : bv;

    // ---- fill W tile (f16 pair words) via cp.async ----
    {
        const uint32_t sWa = (uint32_t)__cvta_generic_to_shared(sW);
        const uint32_t* gw = Wt + y * DD * 64;
        #pragma unroll
        for (int i = 0; i < 16; i++) {
            const int idx4 = i * 128 + tid;       // 0..2047 (16B chunks)
            const int n    = idx4 >> 4;
            const int kwb  = (idx4 & 15) * 4;
            cpa16(sWa + (n * PW + kwb) * 4, gw + n * 64 + kwb);
        }
    }
    // ---- fill X tile: coalesced float4 loads, split to f16 hi/lo ----
    {
        const float4* Xb = (const float4*)(X + (size_t)row0 * DD);
        #pragma unroll
        for (int i = 0; i < 16; i++) {
            const int fidx = i * 128 + tid;       // 0..2047 float4s
            const int r    = fidx >> 5;
            const int c4   = fidx & 31;
            const float4 vv = Xb[fidx];
            uint32_t h0, l0, h1, l1;
            split_h2(vv.x, vv.y, h0, l0);
            split_h2(vv.z, vv.w, h1, l1);
            sXh[r * PW + 2 * c4]     = h0;
            sXh[r * PW + 2 * c4 + 1] = h1;
            sXl[r * PW + 2 * c4]     = l0;
            sXl[r * PW + 2 * c4 + 1] = l1;
        }
    }
    cpa_wait();
    __syncthreads();

    // ---- mainloop: C[16][4] accumulators, init with bias ----
    float C[16][4];
    #pragma unroll
    for (int nt = 0; nt < 16; nt++) {
        const float2 bz = *(const float2*)&bias[nt * 8 + 2 * t];
        C[nt][0] = bz.x; C[nt][1] = bz.y;
        C[nt][2] = bz.x; C[nt][3] = bz.y;
    }
    const int ra = (wq * 16 + g) * PW;
    const int rb = (wq * 16 + g + 8) * PW;
    #pragma unroll
    for (int kt = 0; kt < 8; kt++) {
        uint32_t ahi[4], alo[4];
        const int kb = kt * 8 + t;
        ahi[0] = sXh[ra + kb];     ahi[1] = sXh[rb + kb];
        ahi[2] = sXh[ra + kb + 4]; ahi[3] = sXh[rb + kb + 4];
        alo[0] = sXl[ra + kb];     alo[1] = sXl[rb + kb];
        alo[2] = sXl[ra + kb + 4]; alo[3] = sXl[rb + kb + 4];
        #pragma unroll
        for (int nt = 0; nt < 16; nt++) {
            const int wb = (nt * 8 + g) * PW + kt * 8 + t;
            const uint32_t b0 = sW[wb], b1 = sW[wb + 4];
            mma_f16(C[nt], ahi, b0, b1);
            mma_f16(C[nt], alo, b0, b1);
        }
    }
    __syncthreads();   // sX dead; xsF overlay becomes valid

    // ---- stage C to smem fp32 ----
    #pragma unroll
    for (int nt = 0; nt < 16; nt++) {
        float* p0 = &xsF[(wq * 16 + g) * 132 + nt * 8 + 2 * t];
        float* p1 = &xsF[(wq * 16 + g + 8) * 132 + nt * 8 + 2 * t];
        p0[0] = C[nt][0]; p0[1] = C[nt][1];
        p1[0] = C[nt][2]; p1[1] = C[nt][3];
    }
    __syncthreads();

    // ---- pack & store per output kind ----
    const int bbat = row0 >> 11;
    const int trow = row0 & 2047;

    if (y == 0) {
        #pragma unroll
        for (int r = 0; r < 64; r++)
            Qd[(size_t)(row0 + r) * DD + tid] = xsF[r * 132 + tid];
    } else if (y == 1) {
        // K: 64 rows x 8 heads x 8 f16-pair words = 4096 words
        #pragma unroll
        for (int i = 0; i < 32; i++) {
            const int widx = i * 128 + tid;
            const int r    = widx >> 6;          // 0..63
            const int rem  = widx & 63;
            const int hh2  = rem >> 3;
            const int w    = rem & 7;
            const int c    = hh2 * DK + w * 2;
            const uint32_t word = pack_h2(xsF[r * 132 + c], xsF[r * 132 + c + 1]);
            Kw[((size_t)(bbat * HH + hh2) * TT + trow + r) * 8 + w] = word;
        }
    } else {
        // V^T: 32 pairs x 128 hd = 4096 words
        const int p0 = trow >> 1;
        #pragma unroll
        for (int i = 0; i < 32; i++) {
            const int widx = i * 128 + tid;
            const int hd  = widx >> 5;           // 0..127
            const int pl  = widx & 31;           // 0..31
            const int hh2 = hd >> 4, d = hd & 15;
            const int c   = hh2 * DK + d;
            const uint32_t word = pack_h2(xsF[(2 * pl) * 132 + c],
                                          xsF[(2 * pl + 1) * 132 + c]);
            Vt[((size_t)(bbat * HH + hh2) * DK + d) * (TT / 2) + p0 + pl] = word;
        }
    }
}

// ---------------------------------------------------------------------------
// Output projection + residual + LayerNorm (unchanged)
// ---------------------------------------------------------------------------
__global__ void out_kernel(const float* __restrict__ ctxg,
                           const float* __restrict__ Wo,
                           const float* __restrict__ bo,
                           const float* __restrict__ resid,
                           const float* __restrict__ gamma,
                           const float* __restrict__ beta,
                           float* __restrict__ out)
{
    __shared__ float xs[16][132];
    __shared__ float mrow[16], rrow[16];
    const int tid  = threadIdx.x;
    const int row0 = blockIdx.x * 16;

    #pragma unroll
    for (int r = 0; r < 16; r++)
        xs[r][tid] = ctxg[(size_t)(row0 + r) * DD + tid];
    __syncthreads();

    float acc[16];
    const float bv = bo[tid];
    #pragma unroll
    for (int r = 0; r < 16; r++) acc[r] = bv;

    #pragma unroll 4
    for (int kk = 0; kk < DD; kk += 4) {
        const float w0 = Wo[(kk + 0) * DD + tid];
        const float w1 = Wo[(kk + 1) * DD + tid];
        const float w2 = Wo[(kk + 2) * DD + tid];
        const float w3 = Wo[(kk + 3) * DD + tid];
        #pragma unroll
        for (int r = 0; r < 16; r++) {
            const float4 xv = *(const float4*)&xs[r][kk];
            acc[r] = fmaf(xv.x, w0, fmaf(xv.y, w1, fmaf(xv.z, w2, fmaf(xv.w, w3, acc[r]))));
        }
    }
    __syncthreads();

    #pragma unroll
    for (int r = 0; r < 16; r++) {
        acc[r] += resid[(size_t)(row0 + r) * DD + tid];
        xs[r][tid] = acc[r];
    }
    __syncthreads();

    {
        const int r = tid >> 3, l8 = tid & 7;
        float s = 0.f, s2 = 0.f;
        for (int c = l8; c < 128; c += 8) {
            const float v = xs[r][c];
            s += v; s2 = fmaf(v, v, s2);
        }
        #pragma unroll
        for (int off = 4; off > 0; off >>= 1) {
            s  += __shfl_down_sync(0xffffffffu, s,  off, 8);
            s2 += __shfl_down_sync(0xffffffffu, s2, off, 8);
        }
        if (l8 == 0) {
            const float m   = s * (1.f / 128.f);
            const float var = s2 * (1.f / 128.f) - m * m;
            mrow[r] = m;
            rrow[r] = rsqrtf(var + 1e-5f);
        }
    }
    __syncthreads();

    const float gm = gamma[tid], bt = beta[tid];
    #pragma unroll
    for (int r = 0; r < 16; r++)
        out[(size_t)(row0 + r) * DD + tid] = (acc[r] - mrow[r]) * rrow[r] * gm + bt;
}

// ---------------------------------------------------------------------------
extern "C" void kernel_launch(void* const* d_in, const int* in_sizes, int n_in,
                              void* d_out, int out_size)
{
    const float* queries = (const float*)d_in[0];
    const float* keys    = (const float*)d_in[1];
    const float* values  = (const float*)d_in[2];
    const float* Wq      = (const float*)d_in[3];
    const float* bq      = (const float*)d_in[4];
    const float* Wk      = (const float*)d_in[5];
    const float* bk      = (const float*)d_in[6];
    const float* Wv      = (const float*)d_in[7];
    const float* bv      = (const float*)d_in[8];
    const float* Wo      = (const float*)d_in[9];
    const float* bo      = (const float*)d_in[10];
    const float* gamma   = (const float*)d_in[11];
    const float* beta    = (const float*)d_in[12];

    float* out  = (float*)d_out;
    float* attn = out + (size_t)BB * TT * DD;

    float *Qd, *Cd; uint32_t *Kwp, *Vtp, *Wtp;
    cudaGetSymbolAddress((void**)&Qd,  g_Q);
    cudaGetSymbolAddress((void**)&Kwp, g_Kw);
    cudaGetSymbolAddress((void**)&Vtp, g_Vt);
    cudaGetSymbolAddress((void**)&Cd,  g_ctx);
    cudaGetSymbolAddress((void**)&Wtp, g_Wt);

    const int proj_smem = 256 * PW * 4;   // 69632 bytes
    static int attr_set = 0;
    cudaFuncSetAttribute(proj3_mma_kernel,
                         cudaFuncAttributeMaxDynamicSharedMemorySize, proj_smem);
    (void)attr_set;

    wt_pack_kernel<<<3, 128>>>(Wq, Wk, Wv, Wtp);

    proj3_mma_kernel<<<dim3(BB * TT / 64, 3), 128, proj_smem>>>(
        queries, keys, values, Wtp, bq, bk, bv, Qd, Kwp, Vtp);

    attn_mma_kernel<<<dim3(TT / 64, BB * HH), 128>>>(Qd, Kwp, Vtp, attn, Cd);

    out_kernel<<<BB * TT / 16, 128>>>(Cd, Wo, bo, queries, gamma, beta, out);
}